// round 7
// baseline (speedup 1.0000x reference)
#include <cuda_runtime.h>

#define Hh 64
#define FF 36
#define Ww 8
#define Ss 200
#define KSTRIDE 66   // 5*66 = 330 ≡ 10 (mod 32): LDS.64 at lane-stride-5-rows hits
                     // all 32 banks exactly twice per warp -> conflict-free minimum
#define NTHREADS 256

// smem layout in floats
#define OFF_K    0                        // 200*66 = 13200
#define OFF_M    13200                    // 36*64  = 2304
#define OFF_SCP  (OFF_M + FF*Hh)          // 6*200  = 1200 partial scores per o-group
#define OFF_SC   (OFF_SCP + 6*Ss)         // 200
#define OFF_RED  (OFF_SC + Ss)            // 256
#define OFF_D    (OFF_RED + 256)          // 36
#define OFF_W2   (OFF_D + FF)             // 36
#define OFF_Q    (OFF_W2 + FF)            // 64
#define OFF_MISC (OFF_Q + Hh)             // 4: smax, ssum, b2, prelu_a
#define SMEM_FLOATS (OFF_MISC + 4)        // 17300 floats = 69.2 KB -> 3 CTAs/SM

// 0 = mask is int32 (one word per element), 1 = mask is packed bytes (uint8)
__device__ int g_mask_is_bytes;

__global__ void detect_mask_layout(const unsigned int* __restrict__ m, int nwords) {
    __shared__ int found;
    if (threadIdx.x == 0) found = 0;
    __syncthreads();
    int f = 0;
    for (int i = threadIdx.x; i < nwords; i += blockDim.x)
        f |= (m[i] > 1u);
    if (f) atomicOr(&found, 1);
    __syncthreads();
    if (threadIdx.x == 0) g_mask_is_bytes = found;
}

typedef unsigned long long ull;

__device__ __forceinline__ void ffma2(ull& d, ull a, ull b) {
    asm("fma.rn.f32x2 %0, %1, %2, %0;" : "+l"(d) : "l"(a), "l"(b));
}
// 8B shared load -> one 64-bit reg (adjacent f32 pair)
__device__ __forceinline__ ull lds_u64(unsigned int addr) {
    ull v;
    asm volatile("ld.shared.b64 %0, [%1];" : "=l"(v) : "r"(addr));
    return v;
}
__device__ __forceinline__ void sts_u64(unsigned int addr, ull v) {
    asm volatile("st.shared.b64 [%0], %1;" :: "r"(addr), "l"(v));
}
__device__ __forceinline__ float lo32(ull v) {
    return __uint_as_float((unsigned int)(v & 0xffffffffULL));
}
__device__ __forceinline__ float hi32(ull v) {
    return __uint_as_float((unsigned int)(v >> 32));
}

extern "C" __global__ void __launch_bounds__(NTHREADS, 3)
twb_kernel(const float* __restrict__ query,
           const float* __restrict__ key,
           const float* __restrict__ W1,
           const float* __restrict__ b1,
           const float* __restrict__ prelu_a,
           const float* __restrict__ W2,
           const float* __restrict__ b2,
           const void* __restrict__ mask,
           float* __restrict__ out)
{
    extern __shared__ float sm[];
    const int bw  = blockIdx.x;     // b*W + w
    const int b   = bw >> 3;        // W = 8
    const int tid = threadIdx.x;

    // ---- small loads ----
    if (tid < Hh) sm[OFF_Q + tid]  = query[b * Hh + tid];
    if (tid < FF) sm[OFF_W2 + tid] = W2[tid];
    if (tid == 0) { sm[OFF_MISC + 2] = b2[0]; sm[OFF_MISC + 3] = prelu_a[0]; }
    __syncthreads();

    // ---- stage K tile (200x64) into smem, stride 66 (8B-aligned rows) ----
    {
        const unsigned int ksm = (unsigned int)__cvta_generic_to_shared(&sm[OFF_K]);
        const float4* gk = (const float4*)(key + (size_t)bw * Ss * Hh);
        for (int i = tid; i < Ss * Hh / 4; i += NTHREADS) {
            int s = i >> 4, c = i & 15;
            float4 v = gk[i];
            unsigned int a = ksm + (unsigned)(s * KSTRIDE + c * 4) * 4u;
            sts_u64(a,     ((ull)__float_as_uint(v.y) << 32) | __float_as_uint(v.x));
            sts_u64(a + 8, ((ull)__float_as_uint(v.w) << 32) | __float_as_uint(v.z));
        }
    }

    // ---- build M_b (36x64) and d_b (36) from W1, q ----
    {
        const float* q = &sm[OFF_Q];
        for (int idx = tid; idx < FF * Hh; idx += NTHREADS) {
            int o = idx >> 6, h = idx & 63;
            const float* w = W1 + o * 4 * Hh;
            sm[OFF_M + idx] = w[Hh + h] - w[2 * Hh + h] + w[3 * Hh + h] * q[h];
        }
        if (tid < FF) {
            const float* w = W1 + tid * 4 * Hh;
            float acc = b1[tid];
            #pragma unroll 8
            for (int h = 0; h < Hh; h++)
                acc += (w[h] + w[2 * Hh + h]) * q[h];
            sm[OFF_D + tid] = acc;
        }
    }
    __syncthreads();

    // ==== register-tiled GEMM: 6-output x 5-seq tiles, single pass ====
    // 240 active threads: og = tid/40 (6 groups of 6 outputs), sg = tid%40 (5 s).
    if (tid < 240) {
        const int og = tid / 40;
        const int sg = tid - og * 40;
        const int ob = og * 6;

        const unsigned int kbase = (unsigned int)__cvta_generic_to_shared(
                                       &sm[OFF_K + sg * 5 * KSTRIDE]);
        const unsigned int mbase = (unsigned int)__cvta_generic_to_shared(
                                       &sm[OFF_M + ob * Hh]);

        ull acc[6][5];
        #pragma unroll
        for (int o = 0; o < 6; o++)
            #pragma unroll
            for (int i = 0; i < 5; i++) acc[o][i] = 0ULL;

        #pragma unroll 2
        for (int kp = 0; kp < 32; kp++) {            // 2 k-values per iter
            ull kv[5];
            #pragma unroll
            for (int i = 0; i < 5; i++)
                kv[i] = lds_u64(kbase + (unsigned)(i * KSTRIDE + kp * 2) * 4u);
            #pragma unroll
            for (int o = 0; o < 6; o++) {
                ull mv = lds_u64(mbase + (unsigned)(o * Hh + kp * 2) * 4u);
                #pragma unroll
                for (int i = 0; i < 5; i++)
                    ffma2(acc[o][i], mv, kv[i]);
            }
        }

        // epilogue: h -> PReLU -> dot W2 partial per (og, s)
        const float ap = sm[OFF_MISC + 3];
        #pragma unroll
        for (int i = 0; i < 5; i++) {
            float ps = 0.f;
            #pragma unroll
            for (int o = 0; o < 6; o++) {
                float hv = lo32(acc[o][i]) + hi32(acc[o][i]) + sm[OFF_D + ob + o];
                hv = hv >= 0.f ? hv : ap * hv;
                ps += sm[OFF_W2 + ob + o] * hv;
            }
            sm[OFF_SCP + og * Ss + sg * 5 + i] = ps;
        }
    }
    __syncthreads();

    // ---- combine o-group partials, add bias, mask ----
    if (tid < Ss) {
        float sc = sm[OFF_MISC + 2];
        #pragma unroll
        for (int og = 0; og < 6; og++) sc += sm[OFF_SCP + og * Ss + tid];
        int mk;
        if (g_mask_is_bytes)
            mk = ((const unsigned char*)mask)[(size_t)bw * Ss + tid];
        else
            mk = ((const int*)mask)[(size_t)bw * Ss + tid];
        sm[OFF_SC + tid] = mk ? -10000.0f : sc;
    }
    __syncthreads();

    // ---- softmax over S ----
    if (tid < 32) {
        float m = -3.4e38f;
        for (int i = tid; i < Ss; i += 32) m = fmaxf(m, sm[OFF_SC + i]);
        #pragma unroll
        for (int off = 16; off; off >>= 1)
            m = fmaxf(m, __shfl_xor_sync(0xffffffffu, m, off));
        if (tid == 0) sm[OFF_MISC + 0] = m;
    }
    __syncthreads();
    const float smax = sm[OFF_MISC + 0];
    if (tid < Ss) sm[OFF_SC + tid] = __expf(sm[OFF_SC + tid] - smax);
    __syncthreads();
    if (tid < 32) {
        float sum = 0.f;
        for (int i = tid; i < Ss; i += 32) sum += sm[OFF_SC + i];
        #pragma unroll
        for (int off = 16; off; off >>= 1)
            sum += __shfl_xor_sync(0xffffffffu, sum, off);
        if (tid == 0) sm[OFF_MISC + 1] = sum;
    }
    __syncthreads();
    const float inv = 1.0f / sm[OFF_MISC + 1];

    // ---- weighted sum: out[h] = inv * sum_s e[s]*k[s][h] ----
    {
        int h = tid & 63, g = tid >> 6;   // 4 s-groups x 64 h; lanes consecutive h
        float acc = 0.f;
        for (int s = g; s < Ss; s += 4)
            acc += sm[OFF_SC + s] * sm[OFF_K + s * KSTRIDE + h];
        sm[OFF_RED + g * 64 + h] = acc;
    }
    __syncthreads();
    if (tid < Hh) {
        float v = sm[OFF_RED + tid] + sm[OFF_RED + 64 + tid]
                + sm[OFF_RED + 128 + tid] + sm[OFF_RED + 192 + tid];
        out[(size_t)bw * Hh + tid] = v * inv;
    }
}

extern "C" void kernel_launch(void* const* d_in, const int* in_sizes, int n_in,
                              void* d_out, int out_size) {
    const float* query          = (const float*)d_in[0];
    const float* key            = (const float*)d_in[1];
    const float* W1             = (const float*)d_in[2];
    const float* b1             = (const float*)d_in[3];
    const float* prelu_a        = (const float*)d_in[4];
    const float* W2             = (const float*)d_in[5];
    const float* b2             = (const float*)d_in[6];
    const void*  mask           = (const void*)d_in[7];
    float* out = (float*)d_out;

    const int B = in_sizes[0] / Hh;      // 512
    const int grid = B * Ww;             // 4096 CTAs, one per (b,w)
    const int smem_bytes = SMEM_FLOATS * sizeof(float);   // ~69.2 KB

    detect_mask_layout<<<1, 1024>>>((const unsigned int*)mask, 65536);

    cudaFuncSetAttribute(twb_kernel,
                         cudaFuncAttributeMaxDynamicSharedMemorySize, smem_bytes);
    twb_kernel<<<grid, NTHREADS, smem_bytes>>>(
        query, key, W1, b1, prelu_a, W2, b2, mask, out);
}

// round 8
// speedup vs baseline: 1.5490x; 1.5490x over previous
#include <cuda_runtime.h>

#define Hh 64
#define FF 36
#define Ww 8
#define Ss 200
#define KSTRIDE 66   // 5*66 = 330 ≡ 10 (mod 32): LDS.64 at lane-stride-5-rows hits
                     // all 32 banks exactly twice per warp -> conflict-free minimum
#define NTHREADS 256

// smem layout in floats
#define OFF_K    0                        // 200*66 = 13200
#define OFF_M    13200                    // 36*64  = 2304
#define OFF_SCP  (OFF_M + FF*Hh)          // 6*200  = 1200 partial scores per o-group
#define OFF_SC   (OFF_SCP + 6*Ss)         // 200
#define OFF_RED  (OFF_SC + Ss)            // 256
#define OFF_D    (OFF_RED + 256)          // 36
#define OFF_W2   (OFF_D + FF)             // 36
#define OFF_Q    (OFF_W2 + FF)            // 64
#define OFF_MISC (OFF_Q + Hh)             // 4: smax, ssum, b2, prelu_a
#define SMEM_FLOATS (OFF_MISC + 4)        // 17300 floats = 69.2 KB -> 3 CTAs/SM

// 0 = mask is int32 (one word per element), 1 = mask is packed bytes (uint8)
__device__ int g_mask_is_bytes;

__global__ void detect_mask_layout(const unsigned int* __restrict__ m, int nwords) {
    __shared__ int found;
    if (threadIdx.x == 0) found = 0;
    __syncthreads();
    int f = 0;
    for (int i = threadIdx.x; i < nwords; i += blockDim.x)
        f |= (m[i] > 1u);
    if (f) atomicOr(&found, 1);
    __syncthreads();
    if (threadIdx.x == 0) g_mask_is_bytes = found;
}

typedef unsigned long long ull;

__device__ __forceinline__ void ffma2(ull& d, ull a, ull b) {
    asm("fma.rn.f32x2 %0, %1, %2, %0;" : "+l"(d) : "l"(a), "l"(b));
}
// 8B shared load -> one 64-bit reg (adjacent f32 pair)
__device__ __forceinline__ ull lds_u64(unsigned int addr) {
    ull v;
    asm volatile("ld.shared.b64 %0, [%1];" : "=l"(v) : "r"(addr));
    return v;
}
__device__ __forceinline__ void sts_u64(unsigned int addr, ull v) {
    asm volatile("st.shared.b64 [%0], %1;" :: "r"(addr), "l"(v));
}
__device__ __forceinline__ float lo32(ull v) {
    return __uint_as_float((unsigned int)(v & 0xffffffffULL));
}
__device__ __forceinline__ float hi32(ull v) {
    return __uint_as_float((unsigned int)(v >> 32));
}

extern "C" __global__ void __launch_bounds__(NTHREADS, 3)
twb_kernel(const float* __restrict__ query,
           const float* __restrict__ key,
           const float* __restrict__ W1,
           const float* __restrict__ b1,
           const float* __restrict__ prelu_a,
           const float* __restrict__ W2,
           const float* __restrict__ b2,
           const void* __restrict__ mask,
           float* __restrict__ out)
{
    extern __shared__ float sm[];
    const int bw  = blockIdx.x;     // b*W + w
    const int b   = bw >> 3;        // W = 8
    const int tid = threadIdx.x;

    // ---- small loads ----
    if (tid < Hh) sm[OFF_Q + tid]  = query[b * Hh + tid];
    if (tid < FF) sm[OFF_W2 + tid] = W2[tid];
    if (tid == 0) { sm[OFF_MISC + 2] = b2[0]; sm[OFF_MISC + 3] = prelu_a[0]; }
    __syncthreads();

    // ---- stage K tile (200x64) into smem, stride 66 (8B-aligned rows) ----
    {
        const unsigned int ksm = (unsigned int)__cvta_generic_to_shared(&sm[OFF_K]);
        const float4* gk = (const float4*)(key + (size_t)bw * Ss * Hh);
        for (int i = tid; i < Ss * Hh / 4; i += NTHREADS) {
            int s = i >> 4, c = i & 15;
            float4 v = gk[i];
            unsigned int a = ksm + (unsigned)(s * KSTRIDE + c * 4) * 4u;
            sts_u64(a,     ((ull)__float_as_uint(v.y) << 32) | __float_as_uint(v.x));
            sts_u64(a + 8, ((ull)__float_as_uint(v.w) << 32) | __float_as_uint(v.z));
        }
    }

    // ---- build M_b (36x64) and d_b (36) from W1, q ----
    {
        const float* q = &sm[OFF_Q];
        for (int idx = tid; idx < FF * Hh; idx += NTHREADS) {
            int o = idx >> 6, h = idx & 63;
            const float* w = W1 + o * 4 * Hh;
            sm[OFF_M + idx] = w[Hh + h] - w[2 * Hh + h] + w[3 * Hh + h] * q[h];
        }
        if (tid < FF) {
            const float* w = W1 + tid * 4 * Hh;
            float acc = b1[tid];
            #pragma unroll 8
            for (int h = 0; h < Hh; h++)
                acc += (w[h] + w[2 * Hh + h]) * q[h];
            sm[OFF_D + tid] = acc;
        }
    }
    __syncthreads();

    // ==== register-tiled GEMM: 6-output x 5-seq tiles, single pass ====
    // 240 active threads: og = tid/40 (6 groups of 6 outputs), sg = tid%40 (5 s).
    if (tid < 240) {
        const int og = tid / 40;
        const int sg = tid - og * 40;
        const int ob = og * 6;

        const unsigned int kbase = (unsigned int)__cvta_generic_to_shared(
                                       &sm[OFF_K + sg * 5 * KSTRIDE]);
        const unsigned int mbase = (unsigned int)__cvta_generic_to_shared(
                                       &sm[OFF_M + ob * Hh]);

        ull acc[6][5];
        #pragma unroll
        for (int o = 0; o < 6; o++)
            #pragma unroll
            for (int i = 0; i < 5; i++) acc[o][i] = 0ULL;

        #pragma unroll 1
        for (int kp = 0; kp < 32; kp++) {            // 2 k-values per iter
            ull kv[5];
            #pragma unroll
            for (int i = 0; i < 5; i++)
                kv[i] = lds_u64(kbase + (unsigned)(i * KSTRIDE + kp * 2) * 4u);
            #pragma unroll
            for (int o = 0; o < 6; o++) {
                ull mv = lds_u64(mbase + (unsigned)(o * Hh + kp * 2) * 4u);
                #pragma unroll
                for (int i = 0; i < 5; i++)
                    ffma2(acc[o][i], mv, kv[i]);
            }
        }

        // epilogue: h -> PReLU -> dot W2 partial per (og, s)
        const float ap = sm[OFF_MISC + 3];
        #pragma unroll
        for (int i = 0; i < 5; i++) {
            float ps = 0.f;
            #pragma unroll
            for (int o = 0; o < 6; o++) {
                float hv = lo32(acc[o][i]) + hi32(acc[o][i]) + sm[OFF_D + ob + o];
                hv = hv >= 0.f ? hv : ap * hv;
                ps += sm[OFF_W2 + ob + o] * hv;
            }
            sm[OFF_SCP + og * Ss + sg * 5 + i] = ps;
        }
    }
    __syncthreads();

    // ---- combine o-group partials, add bias, mask ----
    if (tid < Ss) {
        float sc = sm[OFF_MISC + 2];
        #pragma unroll
        for (int og = 0; og < 6; og++) sc += sm[OFF_SCP + og * Ss + tid];
        int mk;
        if (g_mask_is_bytes)
            mk = ((const unsigned char*)mask)[(size_t)bw * Ss + tid];
        else
            mk = ((const int*)mask)[(size_t)bw * Ss + tid];
        sm[OFF_SC + tid] = mk ? -10000.0f : sc;
    }
    __syncthreads();

    // ---- softmax over S ----
    if (tid < 32) {
        float m = -3.4e38f;
        for (int i = tid; i < Ss; i += 32) m = fmaxf(m, sm[OFF_SC + i]);
        #pragma unroll
        for (int off = 16; off; off >>= 1)
            m = fmaxf(m, __shfl_xor_sync(0xffffffffu, m, off));
        if (tid == 0) sm[OFF_MISC + 0] = m;
    }
    __syncthreads();
    const float smax = sm[OFF_MISC + 0];
    if (tid < Ss) sm[OFF_SC + tid] = __expf(sm[OFF_SC + tid] - smax);
    __syncthreads();
    if (tid < 32) {
        float sum = 0.f;
        for (int i = tid; i < Ss; i += 32) sum += sm[OFF_SC + i];
        #pragma unroll
        for (int off = 16; off; off >>= 1)
            sum += __shfl_xor_sync(0xffffffffu, sum, off);
        if (tid == 0) sm[OFF_MISC + 1] = sum;
    }
    __syncthreads();
    const float inv = 1.0f / sm[OFF_MISC + 1];

    // ---- weighted sum: out[h] = inv * sum_s e[s]*k[s][h] ----
    {
        int h = tid & 63, g = tid >> 6;   // 4 s-groups x 64 h; lanes consecutive h
        float acc = 0.f;
        for (int s = g; s < Ss; s += 4)
            acc += sm[OFF_SC + s] * sm[OFF_K + s * KSTRIDE + h];
        sm[OFF_RED + g * 64 + h] = acc;
    }
    __syncthreads();
    if (tid < Hh) {
        float v = sm[OFF_RED + tid] + sm[OFF_RED + 64 + tid]
                + sm[OFF_RED + 128 + tid] + sm[OFF_RED + 192 + tid];
        out[(size_t)bw * Hh + tid] = v * inv;
    }
}

extern "C" void kernel_launch(void* const* d_in, const int* in_sizes, int n_in,
                              void* d_out, int out_size) {
    const float* query          = (const float*)d_in[0];
    const float* key            = (const float*)d_in[1];
    const float* W1             = (const float*)d_in[2];
    const float* b1             = (const float*)d_in[3];
    const float* prelu_a        = (const float*)d_in[4];
    const float* W2             = (const float*)d_in[5];
    const float* b2             = (const float*)d_in[6];
    const void*  mask           = (const void*)d_in[7];
    float* out = (float*)d_out;

    const int B = in_sizes[0] / Hh;      // 512
    const int grid = B * Ww;             // 4096 CTAs, one per (b,w)
    const int smem_bytes = SMEM_FLOATS * sizeof(float);   // ~69.2 KB

    detect_mask_layout<<<1, 1024>>>((const unsigned int*)mask, 65536);

    cudaFuncSetAttribute(twb_kernel,
                         cudaFuncAttributeMaxDynamicSharedMemorySize, smem_bytes);
    twb_kernel<<<grid, NTHREADS, smem_bytes>>>(
        query, key, W1, b1, prelu_a, W2, b2, mask, out);
}